// round 1
// baseline (speedup 1.0000x reference)
#include <cuda_runtime.h>
#include <math.h>

#define BB 64
#define TT 512
#define DD 512
#define HH 512
#define G4H 2048  // 4*H

// -------- device scratch (no cudaMalloc allowed) --------
__device__ float g_Zx[2][TT * BB][G4H];      // x-projection + bias, [dir][t*B+b][4H]  (512 MB)
__device__ float g_h[2][2][HH][BB];          // hidden state, transposed [dir][pingpong][k][b]
__device__ float g_c[2][BB * HH];            // cell state [dir][b*H+h]

// -------- zero state each replay (determinism under graph capture) --------
__global__ void init_kernel() {
    int i = blockIdx.x * blockDim.x + threadIdx.x;
    float* h = &g_h[0][0][0][0];
    float* c = &g_c[0][0];
    int nh = 2 * 2 * HH * BB;
    int nc = 2 * BB * HH;
    if (i < nh) h[i] = 0.f;
    if (i < nc) c[i] = 0.f;
}

// -------- x-projection GEMM: Zx[dir][t*B+b][n] = x[b][t][:] . W[dir][:D][n] + bias[n] --------
// grid (M/128=256, N/128=16, 2), block 256. 128x128 tile, 8x8 per thread, BK=8.
__global__ void pregemm(const float* __restrict__ x,
                        const float* __restrict__ Wfw, const float* __restrict__ bfw,
                        const float* __restrict__ Wbw, const float* __restrict__ bbw) {
    int dir = blockIdx.z;
    const float* Wm   = dir ? Wbw : Wfw;
    const float* bias = dir ? bbw : bfw;

    __shared__ float As[8][128];
    __shared__ float Bs[8][128];

    int tid = threadIdx.x;
    int m0 = blockIdx.x * 128;
    int n0 = blockIdx.y * 128;

    // A-load mapping: one float4 per thread per iter
    int a_m  = tid >> 1;            // 0..127
    int a_k4 = (tid & 1) * 4;       // 0 or 4
    int gm   = m0 + a_m;            // global M index = t*B + b
    int a_t  = gm >> 6;             // / B
    int a_b  = gm & 63;             // % B
    const float* a_ptr = x + ((size_t)a_b * TT + a_t) * DD;

    // B-load mapping
    int b_k = tid >> 5;             // 0..7
    int b_n = (tid & 31) * 4;       // 0..124

    float acc[8][8];
#pragma unroll
    for (int i = 0; i < 8; i++)
#pragma unroll
        for (int j = 0; j < 8; j++) acc[i][j] = 0.f;

    int ty = tid >> 4;              // 0..15 -> rows ty*8
    int tx = tid & 15;              // 0..15 -> cols tx*8

    for (int k0 = 0; k0 < DD; k0 += 8) {
        float4 av = *(const float4*)(a_ptr + k0 + a_k4);
        float4 bv = *(const float4*)(Wm + (size_t)(k0 + b_k) * G4H + n0 + b_n);
        As[a_k4 + 0][a_m] = av.x;
        As[a_k4 + 1][a_m] = av.y;
        As[a_k4 + 2][a_m] = av.z;
        As[a_k4 + 3][a_m] = av.w;
        *(float4*)&Bs[b_k][b_n] = bv;
        __syncthreads();

#pragma unroll
        for (int kk = 0; kk < 8; kk++) {
            float4 a0 = *(float4*)&As[kk][ty * 8];
            float4 a1 = *(float4*)&As[kk][ty * 8 + 4];
            float4 b0 = *(float4*)&Bs[kk][tx * 8];
            float4 b1 = *(float4*)&Bs[kk][tx * 8 + 4];
            float ar[8] = {a0.x, a0.y, a0.z, a0.w, a1.x, a1.y, a1.z, a1.w};
            float br[8] = {b0.x, b0.y, b0.z, b0.w, b1.x, b1.y, b1.z, b1.w};
#pragma unroll
            for (int i = 0; i < 8; i++)
#pragma unroll
                for (int j = 0; j < 8; j++) acc[i][j] += ar[i] * br[j];
        }
        __syncthreads();
    }

    // write with bias folded in
#pragma unroll
    for (int i = 0; i < 8; i++) {
        int m = m0 + ty * 8 + i;
        float* row = &g_Zx[dir][m][n0 + tx * 8];
        const float* bp = bias + n0 + tx * 8;
#pragma unroll
        for (int j = 0; j < 8; j++) row[j] = acc[i][j] + bp[j];
    }
}

// -------- one recurrent step, both directions fused --------
// grid (64 h-blocks, 2 dirs), block 256 = 2 K-groups x 128 threads.
// Each block: z[64 batch x (8 h-idx x 4 gates)] = h_prev @ Wh(cols) ; then activations + c/h update.
__global__ void lstm_step(const float* __restrict__ Wfw,
                          const float* __restrict__ Wbw,
                          float* __restrict__ out, int t) {
    int dir = blockIdx.y;
    int hb  = blockIdx.x;        // 0..63
    int h0  = hb * 8;
    const float* Wm = dir ? Wbw : Wfw;
    int tin = dir ? (TT - 1 - t) : t;
    int buf = t & 1;

    __shared__ float h_s[2][32][64];      // [kgroup][k][b]
    __shared__ float w_s[2][32][32];      // [kgroup][k][c] ; c = g*8 + (h - h0)
    __shared__ float z_s[2][64][33];      // partial z per kgroup, padded

    int tid = threadIdx.x;    // 0..255
    int kg  = tid >> 7;       // K-group 0/1
    int wt  = tid & 127;
    int ty  = wt >> 3;        // 0..15 -> batch rows ty*4
    int tx  = wt & 7;         // 0..7  -> cols tx*4

    float acc[4][4];
#pragma unroll
    for (int i = 0; i < 4; i++)
#pragma unroll
        for (int j = 0; j < 4; j++) acc[i][j] = 0.f;

    for (int it = 0; it < 8; ++it) {
        int kbase = kg * 256 + it * 32;
        // load h tile: 32 k-rows x 64 b, 4 float4 per thread
#pragma unroll
        for (int p = 0; p < 4; ++p) {
            int r  = (wt >> 4) + p * 8;     // 0..31
            int c4 = (wt & 15) * 4;         // 0..60
            *(float4*)&h_s[kg][r][c4] = *(const float4*)&g_h[dir][buf][kbase + r][c4];
        }
        // load W tile: 32 k-rows x 32 gathered cols, 2 float4 per thread
#pragma unroll
        for (int q = 0; q < 2; ++q) {
            int idx = wt * 2 + q;
            int r   = idx >> 3;             // 0..31
            int col = (idx & 7) * 4;        // 0..28
            int g   = col >> 3;
            int hl  = col & 7;              // 0 or 4
            *(float4*)&w_s[kg][r][col] =
                *(const float4*)(Wm + (size_t)(DD + kbase + r) * G4H + g * 512 + h0 + hl);
        }
        __syncthreads();
#pragma unroll
        for (int kk = 0; kk < 32; ++kk) {
            float4 a = *(float4*)&h_s[kg][kk][ty * 4];
            float4 b = *(float4*)&w_s[kg][kk][tx * 4];
            acc[0][0] += a.x * b.x; acc[0][1] += a.x * b.y; acc[0][2] += a.x * b.z; acc[0][3] += a.x * b.w;
            acc[1][0] += a.y * b.x; acc[1][1] += a.y * b.y; acc[1][2] += a.y * b.z; acc[1][3] += a.y * b.w;
            acc[2][0] += a.z * b.x; acc[2][1] += a.z * b.y; acc[2][2] += a.z * b.z; acc[2][3] += a.z * b.w;
            acc[3][0] += a.w * b.x; acc[3][1] += a.w * b.y; acc[3][2] += a.w * b.z; acc[3][3] += a.w * b.w;
        }
        __syncthreads();
    }

    // stash partial sums
#pragma unroll
    for (int i = 0; i < 4; i++)
#pragma unroll
        for (int j = 0; j < 4; j++)
            z_s[kg][ty * 4 + i][tx * 4 + j] = acc[i][j];
    __syncthreads();

    // pointwise LSTM update: 512 (b, h) pairs over 256 threads
    for (int u = tid; u < 512; u += 256) {
        int b  = u >> 3;
        int hl = u & 7;
        int hh = h0 + hl;
        const float* zx = &g_Zx[dir][tin * BB + b][0];
        float zi = z_s[0][b][0 * 8 + hl] + z_s[1][b][0 * 8 + hl] + zx[0 * 512 + hh];
        float zj = z_s[0][b][1 * 8 + hl] + z_s[1][b][1 * 8 + hl] + zx[1 * 512 + hh];
        float zf = z_s[0][b][2 * 8 + hl] + z_s[1][b][2 * 8 + hl] + zx[2 * 512 + hh];
        float zo = z_s[0][b][3 * 8 + hl] + z_s[1][b][3 * 8 + hl] + zx[3 * 512 + hh];

        float ig = 1.f / (1.f + expf(-zi));
        float jg = tanhf(zj);
        float fg = 1.f / (1.f + expf(-(zf + 1.f)));
        float og = 1.f / (1.f + expf(-zo));

        float cprev = g_c[dir][b * HH + hh];
        float cnew  = fg * cprev + ig * jg;
        float hnew  = og * tanhf(cnew);

        g_c[dir][b * HH + hh] = cnew;
        g_h[dir][buf ^ 1][hh][b] = hnew;
        out[((size_t)b * TT + tin) * (2 * HH) + dir * HH + hh] = hnew;
    }
}

extern "C" void kernel_launch(void* const* d_in, const int* in_sizes, int n_in,
                              void* d_out, int out_size) {
    const float* x   = (const float*)d_in[0];
    const float* Wfw = (const float*)d_in[1];
    const float* bfw = (const float*)d_in[2];
    const float* Wbw = (const float*)d_in[3];
    const float* bbw = (const float*)d_in[4];
    float* out = (float*)d_out;

    // zero h/c state
    init_kernel<<<(2 * 2 * HH * BB + 255) / 256, 256>>>();

    // x-projection for both directions (bias folded in)
    pregemm<<<dim3((TT * BB) / 128, G4H / 128, 2), 256>>>(x, Wfw, bfw, Wbw, bbw);

    // 512 recurrent steps, both directions per launch
    for (int t = 0; t < TT; ++t) {
        lstm_step<<<dim3(64, 2), 256>>>(Wfw, Wbw, out, t);
    }
}

// round 2
// speedup vs baseline: 1.0858x; 1.0858x over previous
#include <cuda_runtime.h>
#include <math.h>

#define BB 64
#define TT 512
#define DD 512
#define HH 512
#define G4H 2048  // 4*H

typedef unsigned long long ull;

// -------- device scratch (no cudaMalloc allowed) --------
__device__ float g_Zx[2][TT * BB][G4H];      // x-projection + bias, [dir][t*B+b][4H]
__device__ float g_h[2][2][HH][BB];          // hidden state, [dir][pingpong][k][b]
__device__ volatile unsigned g_phase[2];     // grid-barrier phase per direction
__device__ unsigned g_arrive[2];             // grid-barrier arrival counter per dir

// f32x2 packed FMA (sm_100+): d.lo = a.lo*b.lo+c.lo ; d.hi = a.hi*b.hi+c.hi
#define FMA2(d, a, b, c) \
    asm("fma.rn.f32x2 %0, %1, %2, %3;" : "=l"(d) : "l"(a), "l"(b), "l"(c))
// duplicate one fp32 into both lanes of an f32x2
#define DUP2(d, x) \
    asm("mov.b64 %0, {%1, %1};" : "=l"(d) : "r"(__float_as_uint(x)))

// -------- zero state + barrier vars each replay (determinism) --------
__global__ void init_kernel() {
    int i = blockIdx.x * blockDim.x + threadIdx.x;
    float* h = &g_h[0][0][0][0];
    int nh = 2 * 2 * HH * BB;
    if (i < nh) h[i] = 0.f;
    if (i == 0) {
        g_phase[0] = 0; g_phase[1] = 0;
        g_arrive[0] = 0; g_arrive[1] = 0;
    }
}

// -------- x-projection GEMM: Zx[dir][t*B+b][n] = x[b][t][:] . W[dir][:D][n] + bias --------
__global__ void pregemm(const float* __restrict__ x,
                        const float* __restrict__ Wfw, const float* __restrict__ bfw,
                        const float* __restrict__ Wbw, const float* __restrict__ bbw) {
    int dir = blockIdx.z;
    const float* Wm   = dir ? Wbw : Wfw;
    const float* bias = dir ? bbw : bfw;

    __shared__ float As[8][128];
    __shared__ float Bs[8][128];

    int tid = threadIdx.x;
    int m0 = blockIdx.x * 128;
    int n0 = blockIdx.y * 128;

    int a_m  = tid >> 1;
    int a_k4 = (tid & 1) * 4;
    int gm   = m0 + a_m;
    int a_t  = gm >> 6;
    int a_b  = gm & 63;
    const float* a_ptr = x + ((size_t)a_b * TT + a_t) * DD;

    int b_k = tid >> 5;
    int b_n = (tid & 31) * 4;

    float acc[8][8];
#pragma unroll
    for (int i = 0; i < 8; i++)
#pragma unroll
        for (int j = 0; j < 8; j++) acc[i][j] = 0.f;

    int ty = tid >> 4;
    int tx = tid & 15;

    for (int k0 = 0; k0 < DD; k0 += 8) {
        float4 av = *(const float4*)(a_ptr + k0 + a_k4);
        float4 bv = *(const float4*)(Wm + (size_t)(k0 + b_k) * G4H + n0 + b_n);
        As[a_k4 + 0][a_m] = av.x;
        As[a_k4 + 1][a_m] = av.y;
        As[a_k4 + 2][a_m] = av.z;
        As[a_k4 + 3][a_m] = av.w;
        *(float4*)&Bs[b_k][b_n] = bv;
        __syncthreads();

#pragma unroll
        for (int kk = 0; kk < 8; kk++) {
            float4 a0 = *(float4*)&As[kk][ty * 8];
            float4 a1 = *(float4*)&As[kk][ty * 8 + 4];
            float4 b0 = *(float4*)&Bs[kk][tx * 8];
            float4 b1 = *(float4*)&Bs[kk][tx * 8 + 4];
            float ar[8] = {a0.x, a0.y, a0.z, a0.w, a1.x, a1.y, a1.z, a1.w};
            float br[8] = {b0.x, b0.y, b0.z, b0.w, b1.x, b1.y, b1.z, b1.w};
#pragma unroll
            for (int i = 0; i < 8; i++)
#pragma unroll
                for (int j = 0; j < 8; j++) acc[i][j] += ar[i] * br[j];
        }
        __syncthreads();
    }

#pragma unroll
    for (int i = 0; i < 8; i++) {
        int m = m0 + ty * 8 + i;
        float* row = &g_Zx[dir][m][n0 + tx * 8];
        const float* bp = bias + n0 + tx * 8;
#pragma unroll
        for (int j = 0; j < 8; j++) row[j] = acc[i][j] + bp[j];
    }
}

// -------- per-direction grid barrier (all 64 CTAs of a direction) --------
__device__ __forceinline__ void grid_barrier(int dir, unsigned target) {
    __syncthreads();
    if (threadIdx.x == 0) {
        __threadfence();
        unsigned old = atomicAdd(&g_arrive[dir], 1);
        if (old == 63) {
            g_arrive[dir] = 0;
            __threadfence();
            g_phase[dir] = target;
        } else {
            while (g_phase[dir] < target) { __nanosleep(32); }
            __threadfence();
        }
    }
    __syncthreads();
}

// -------- persistent recurrent kernel: all 512 steps, both dirs --------
// grid (64 h-blocks, 2 dirs), 256 threads = 2 K-groups x 128.
// Dynamic smem: w_s[512][32] resident (64KB) + h_s[2][32][64] (16KB) + z_s[2][64][33] (~17KB)
#define SM_W   (512 * 32)
#define SM_H   (2 * 32 * 64)
#define SM_Z   (2 * 64 * 33)
#define SMEM_FLOATS (SM_W + SM_H + SM_Z)

__global__ void __launch_bounds__(256, 1)
lstm_persist(const float* __restrict__ Wfw, const float* __restrict__ Wbw,
             float* __restrict__ out) {
    extern __shared__ float sm[];
    float* w_s = sm;                    // [512][32]
    float* h_sb = sm + SM_W;            // [2][32][64]
    float* z_sb = sm + SM_W + SM_H;     // [2][64][33]

    int dir = blockIdx.y;
    int hb  = blockIdx.x;
    int h0  = hb * 8;
    const float* Wm = dir ? Wbw : Wfw;

    int tid = threadIdx.x;
    int kg  = tid >> 7;      // K-group 0/1 (k in [kg*256, kg*256+256))
    int wt  = tid & 127;
    int ty  = wt >> 2;       // 0..31 -> batch rows ty*2
    int tx  = wt & 3;        // 0..3  -> cols tx*8 (8 cols as 4 f32x2 pairs)

    float* h_s = h_sb + kg * (32 * 64);
    float* z_s0 = z_sb;             // kgroup 0 partials [64][33]
    float* z_s1 = z_sb + 64 * 33;   // kgroup 1 partials

    // ---- load resident W slice: rows DD..DD+511, gathered 32 cols (4 gates x 8 h) ----
    for (int idx = tid; idx < 4096; idx += 256) {
        int row = idx >> 3;
        int c4  = (idx & 7) * 4;     // 0,4,...,28
        int g   = c4 >> 3;
        int hl  = c4 & 7;            // 0 or 4
        *(float4*)&w_s[row * 32 + c4] =
            *(const float4*)(Wm + (size_t)(DD + row) * G4H + g * 512 + h0 + hl);
    }

    // pointwise mapping: this thread owns u = tid and u = tid+256 -> (b,hl) pairs
    int pb[2], phl[2];
#pragma unroll
    for (int p = 0; p < 2; p++) { int u = tid + p * 256; pb[p] = u >> 3; phl[p] = u & 7; }
    float c_reg[2] = {0.f, 0.f};

    // h-staging load mapping (per kgroup): 4 float4 per thread covering 32x64
    int hr = wt >> 4;            // 0..7 (+p*8)
    int hc = (wt & 15) * 4;      // 0..60

    __syncthreads();

#pragma unroll 1
    for (int t = 0; t < TT; ++t) {
        int tin = dir ? (TT - 1 - t) : t;
        int buf = t & 1;
        const float* hsrc = &g_h[dir][buf][0][0];

        // ---- prefetch Zx for this step into registers (hidden behind GEMM) ----
        float rzx[2][4];
#pragma unroll
        for (int p = 0; p < 2; p++) {
            const float* zp = &g_Zx[dir][tin * BB + pb[p]][h0 + phl[p]];
#pragma unroll
            for (int g = 0; g < 4; g++) rzx[p][g] = zp[g * 512];
        }

        // ---- prefetch h tile for it=0 ----
        float4 pre[4];
        {
            int kbase = kg * 256;
#pragma unroll
            for (int p = 0; p < 4; p++)
                pre[p] = *(const float4*)&hsrc[(kbase + hr + p * 8) * 64 + hc];
        }

        ull acc[2][4];
#pragma unroll
        for (int i = 0; i < 2; i++)
#pragma unroll
            for (int p = 0; p < 4; p++) acc[i][p] = 0ull;

#pragma unroll 1
        for (int it = 0; it < 8; ++it) {
            __syncthreads();
#pragma unroll
            for (int p = 0; p < 4; p++)
                *(float4*)&h_s[(hr + p * 8) * 64 + hc] = pre[p];
            __syncthreads();
            if (it < 7) {
                int kbase = kg * 256 + (it + 1) * 32;
#pragma unroll
                for (int p = 0; p < 4; p++)
                    pre[p] = *(const float4*)&hsrc[(kbase + hr + p * 8) * 64 + hc];
            }
            int kb = kg * 256 + it * 32;
#pragma unroll
            for (int kk = 0; kk < 32; ++kk) {
                float2 a = *(const float2*)&h_s[kk * 64 + ty * 2];
                ull a0, a1;
                DUP2(a0, a.x);
                DUP2(a1, a.y);
                const float* wrow = &w_s[(kb + kk) * 32 + tx * 8];
                ulonglong2 bq0 = *(const ulonglong2*)(wrow);      // pairs (c0,c1),(c2,c3)
                ulonglong2 bq1 = *(const ulonglong2*)(wrow + 4);  // pairs (c4,c5),(c6,c7)
                FMA2(acc[0][0], a0, bq0.x, acc[0][0]);
                FMA2(acc[0][1], a0, bq0.y, acc[0][1]);
                FMA2(acc[0][2], a0, bq1.x, acc[0][2]);
                FMA2(acc[0][3], a0, bq1.y, acc[0][3]);
                FMA2(acc[1][0], a1, bq0.x, acc[1][0]);
                FMA2(acc[1][1], a1, bq0.y, acc[1][1]);
                FMA2(acc[1][2], a1, bq1.x, acc[1][2]);
                FMA2(acc[1][3], a1, bq1.y, acc[1][3]);
            }
        }

        // ---- stash partials ----
        __syncthreads();
        {
            float* zout = (kg == 0 ? z_s0 : z_s1);
#pragma unroll
            for (int i = 0; i < 2; i++) {
                float* row = &zout[(ty * 2 + i) * 33 + tx * 8];
#pragma unroll
                for (int p = 0; p < 4; p++) {
                    unsigned lo = (unsigned)(acc[i][p] & 0xffffffffull);
                    unsigned hi = (unsigned)(acc[i][p] >> 32);
                    row[p * 2 + 0] = __uint_as_float(lo);
                    row[p * 2 + 1] = __uint_as_float(hi);
                }
            }
        }
        __syncthreads();

        // ---- pointwise LSTM update (c in registers) ----
#pragma unroll
        for (int p = 0; p < 2; p++) {
            int b = pb[p], hl = phl[p];
            float zi = z_s0[b * 33 + 0 + hl] + z_s1[b * 33 + 0 + hl] + rzx[p][0];
            float zj = z_s0[b * 33 + 8 + hl] + z_s1[b * 33 + 8 + hl] + rzx[p][1];
            float zf = z_s0[b * 33 + 16 + hl] + z_s1[b * 33 + 16 + hl] + rzx[p][2];
            float zo = z_s0[b * 33 + 24 + hl] + z_s1[b * 33 + 24 + hl] + rzx[p][3];

            float ig = 1.f / (1.f + expf(-zi));
            float jg = tanhf(zj);
            float fg = 1.f / (1.f + expf(-(zf + 1.f)));
            float og = 1.f / (1.f + expf(-zo));

            float cnew = fg * c_reg[p] + ig * jg;
            float hnew = og * tanhf(cnew);
            c_reg[p] = cnew;

            g_h[dir][buf ^ 1][h0 + hl][b] = hnew;
            out[((size_t)b * TT + tin) * (2 * HH) + dir * HH + h0 + hl] = hnew;
        }

        __threadfence();
        grid_barrier(dir, (unsigned)(t + 1));
    }
}

extern "C" void kernel_launch(void* const* d_in, const int* in_sizes, int n_in,
                              void* d_out, int out_size) {
    const float* x   = (const float*)d_in[0];
    const float* Wfw = (const float*)d_in[1];
    const float* bfw = (const float*)d_in[2];
    const float* Wbw = (const float*)d_in[3];
    const float* bbw = (const float*)d_in[4];
    float* out = (float*)d_out;

    static int attr_done = 0;
    if (!attr_done) {
        cudaFuncSetAttribute(lstm_persist, cudaFuncAttributeMaxDynamicSharedMemorySize,
                             SMEM_FLOATS * sizeof(float));
        attr_done = 1;
    }

    // zero h state + barrier vars
    init_kernel<<<(2 * 2 * HH * BB + 255) / 256, 256>>>();

    // x-projection for both directions (bias folded in)
    pregemm<<<dim3((TT * BB) / 128, G4H / 128, 2), 256>>>(x, Wfw, bfw, Wbw, bbw);

    // one persistent kernel runs all 512 steps for both directions
    lstm_persist<<<dim3(64, 2), 256, SMEM_FLOATS * sizeof(float)>>>(Wfw, Wbw, out);
}

// round 3
// speedup vs baseline: 1.1782x; 1.0852x over previous
#include <cuda_runtime.h>
#include <math.h>

#define BB 64
#define TT 512
#define DD 512
#define HH 512
#define G4H 2048  // 4*H

typedef unsigned long long ull;

// -------- device scratch (no cudaMalloc allowed) --------
__device__ float g_Zx[2][TT * BB][G4H];      // x-projection + bias, [dir][t*B+b][4H]
__device__ float g_h[2][2][HH][BB];          // hidden state, [dir][pingpong][k][b]
__device__ volatile unsigned g_phase[2];     // grid-barrier phase per direction
__device__ unsigned g_arrive[2];             // grid-barrier arrival counter per dir

// f32x2 packed FMA (sm_100+)
#define FMA2(d, a, b, c) \
    asm("fma.rn.f32x2 %0, %1, %2, %3;" : "=l"(d) : "l"(a), "l"(b), "l"(c))
#define DUP2(d, x) \
    asm("mov.b64 %0, {%1, %1};" : "=l"(d) : "r"(__float_as_uint(x)))
#define UNPK2(lo, hi, v) \
    asm("mov.b64 {%0, %1}, %2;" : "=r"(lo), "=r"(hi) : "l"(v))

// -------- zero state + barrier vars each replay (determinism) --------
__global__ void init_kernel() {
    int i = blockIdx.x * blockDim.x + threadIdx.x;
    float* h = &g_h[0][0][0][0];
    int nh = 2 * 2 * HH * BB;
    if (i < nh) h[i] = 0.f;
    if (i == 0) {
        g_phase[0] = 0; g_phase[1] = 0;
        g_arrive[0] = 0; g_arrive[1] = 0;
    }
}

// -------- x-projection GEMM (FFMA2): Zx[dir][t*B+b][n] = x . W[:D] + bias --------
// grid (N/128=16, M/128=256, 2), 256 threads. 128x128 tile, BK=16, double buffered.
// Per thread 8(M)x8(N); M handled as 4 f32x2 pairs (M-consecutive floats in smem).
__global__ void __launch_bounds__(256, 2)
pregemm(const float* __restrict__ x,
        const float* __restrict__ Wfw, const float* __restrict__ bfw,
        const float* __restrict__ Wbw, const float* __restrict__ bbw) {
    int dir = blockIdx.z;
    const float* Wm   = dir ? Wbw : Wfw;
    const float* bias = dir ? bbw : bfw;

    __shared__ float As[2][16][128];
    __shared__ float Bs[2][16][128];

    int tid = threadIdx.x;
    int n0 = blockIdx.x * 128;
    int m0 = blockIdx.y * 128;

    // A global-load mapping: 128 rows x 16 k = 2048 floats; 8/thread as 2 float4
    int a_m = tid >> 1;             // 0..127
    int a_k = (tid & 1) * 8;        // 0 or 8
    int gm  = m0 + a_m;
    int a_t = gm >> 6;
    int a_b = gm & 63;
    const float* a_ptr = x + ((size_t)a_b * TT + a_t) * DD + a_k;

    // B global-load mapping: 16 k-rows x 128 n; 8/thread as 2 float4
    int b_k = tid >> 4;             // 0..15
    int b_n = (tid & 15) * 8;       // 0..120
    const float* b_ptr = Wm + (size_t)b_k * G4H + n0 + b_n;

    int ty = tid >> 4;              // 0..15 -> M rows ty*8 (4 pairs)
    int tx = tid & 15;              // 0..15 -> N cols tx*8

    ull acc[4][8];
#pragma unroll
    for (int i = 0; i < 4; i++)
#pragma unroll
        for (int j = 0; j < 8; j++) acc[i][j] = 0ull;

    // ---- prologue: load tile 0 ----
    float4 ar0 = *(const float4*)(a_ptr);
    float4 ar1 = *(const float4*)(a_ptr + 4);
    float4 br0 = *(const float4*)(b_ptr);
    float4 br1 = *(const float4*)(b_ptr + 4);
    {
        float* as = &As[0][0][a_m];
        as[(a_k + 0) * 128] = ar0.x; as[(a_k + 1) * 128] = ar0.y;
        as[(a_k + 2) * 128] = ar0.z; as[(a_k + 3) * 128] = ar0.w;
        as[(a_k + 4) * 128] = ar1.x; as[(a_k + 5) * 128] = ar1.y;
        as[(a_k + 6) * 128] = ar1.z; as[(a_k + 7) * 128] = ar1.w;
        *(float4*)&Bs[0][b_k][b_n] = br0;
        *(float4*)&Bs[0][b_k][b_n + 4] = br1;
    }
    __syncthreads();

    int buf = 0;
#pragma unroll 1
    for (int k0 = 0; k0 < DD / 16; ++k0) {
        // prefetch next tile (global; in flight during compute)
        if (k0 < DD / 16 - 1) {
            const float* ap = a_ptr + (k0 + 1) * 16;
            const float* bp = b_ptr + (size_t)(k0 + 1) * 16 * G4H;
            ar0 = *(const float4*)(ap);
            ar1 = *(const float4*)(ap + 4);
            br0 = *(const float4*)(bp);
            br1 = *(const float4*)(bp + 4);
        }
#pragma unroll
        for (int kk = 0; kk < 16; ++kk) {
            ulonglong2 a01 = *(const ulonglong2*)&As[buf][kk][ty * 8];
            ulonglong2 a23 = *(const ulonglong2*)&As[buf][kk][ty * 8 + 4];
            float4 bv0 = *(const float4*)&Bs[buf][kk][tx * 8];
            float4 bv1 = *(const float4*)&Bs[buf][kk][tx * 8 + 4];
            ull bd[8];
            DUP2(bd[0], bv0.x); DUP2(bd[1], bv0.y); DUP2(bd[2], bv0.z); DUP2(bd[3], bv0.w);
            DUP2(bd[4], bv1.x); DUP2(bd[5], bv1.y); DUP2(bd[6], bv1.z); DUP2(bd[7], bv1.w);
            ull ap[4] = {a01.x, a01.y, a23.x, a23.y};
#pragma unroll
            for (int i = 0; i < 4; i++)
#pragma unroll
                for (int j = 0; j < 8; j++) FMA2(acc[i][j], ap[i], bd[j], acc[i][j]);
        }
        if (k0 < DD / 16 - 1) {
            int nb = buf ^ 1;
            float* as = &As[nb][0][a_m];
            as[(a_k + 0) * 128] = ar0.x; as[(a_k + 1) * 128] = ar0.y;
            as[(a_k + 2) * 128] = ar0.z; as[(a_k + 3) * 128] = ar0.w;
            as[(a_k + 4) * 128] = ar1.x; as[(a_k + 5) * 128] = ar1.y;
            as[(a_k + 6) * 128] = ar1.z; as[(a_k + 7) * 128] = ar1.w;
            *(float4*)&Bs[nb][b_k][b_n] = br0;
            *(float4*)&Bs[nb][b_k][b_n + 4] = br1;
            __syncthreads();
            buf = nb;
        }
    }

    // ---- epilogue: unpack pairs, add bias, store ----
    float bvals[8];
#pragma unroll
    for (int j = 0; j < 8; j++) bvals[j] = bias[n0 + tx * 8 + j];

#pragma unroll
    for (int i = 0; i < 4; i++) {
        float lo[8], hi[8];
#pragma unroll
        for (int j = 0; j < 8; j++) {
            unsigned l, h;
            UNPK2(l, h, acc[i][j]);
            lo[j] = __uint_as_float(l) + bvals[j];
            hi[j] = __uint_as_float(h) + bvals[j];
        }
        int m = m0 + ty * 8 + i * 2;
        float* r0 = &g_Zx[dir][m][n0 + tx * 8];
        float* r1 = &g_Zx[dir][m + 1][n0 + tx * 8];
        *(float4*)r0       = make_float4(lo[0], lo[1], lo[2], lo[3]);
        *(float4*)(r0 + 4) = make_float4(lo[4], lo[5], lo[6], lo[7]);
        *(float4*)r1       = make_float4(hi[0], hi[1], hi[2], hi[3]);
        *(float4*)(r1 + 4) = make_float4(hi[4], hi[5], hi[6], hi[7]);
    }
}

// -------- per-direction grid barrier (all 64 CTAs of a direction) --------
__device__ __forceinline__ void grid_barrier(int dir, unsigned target) {
    __syncthreads();
    if (threadIdx.x == 0) {
        __threadfence();
        unsigned old = atomicAdd(&g_arrive[dir], 1);
        if (old == 63) {
            g_arrive[dir] = 0;
            __threadfence();
            g_phase[dir] = target;
        } else {
            while (g_phase[dir] < target) { __nanosleep(32); }
            __threadfence();
        }
    }
    __syncthreads();
}

// -------- persistent recurrent kernel: all 512 steps, both dirs --------
// grid (64 h-blocks, 2 dirs), 512 threads = 4 K-groups x 128.
#define SM_W   (512 * 32)          // resident W slice
#define SM_H   (4 * 32 * 64)       // h staging per kgroup
#define SM_Z   (4 * 64 * 33)       // partial z per kgroup
#define SMEM_FLOATS (SM_W + SM_H + SM_Z)

__global__ void __launch_bounds__(512, 1)
lstm_persist(const float* __restrict__ Wfw, const float* __restrict__ Wbw,
             float* __restrict__ out) {
    extern __shared__ float sm[];
    float* w_s  = sm;                   // [512][32]
    float* h_sb = sm + SM_W;            // [4][32][64]
    float* z_sb = sm + SM_W + SM_H;     // [4][64][33]

    int dir = blockIdx.y;
    int hb  = blockIdx.x;
    int h0  = hb * 8;
    const float* Wm = dir ? Wbw : Wfw;

    int tid = threadIdx.x;     // 0..511
    int kg  = tid >> 7;        // K-group 0..3 (k in [kg*128, kg*128+128))
    int wt  = tid & 127;
    int ty  = wt >> 2;         // 0..31 -> batch rows ty*2
    int tx  = wt & 3;          // 0..3  -> cols tx*8

    float* h_s = h_sb + kg * (32 * 64);

    // ---- load resident W slice: rows DD..DD+511, gathered 32 cols ----
    for (int idx = tid; idx < 4096; idx += 512) {
        int row = idx >> 3;
        int c4  = (idx & 7) * 4;
        int g   = c4 >> 3;
        int hl  = c4 & 7;
        *(float4*)&w_s[row * 32 + c4] =
            *(const float4*)(Wm + (size_t)(DD + row) * G4H + g * 512 + h0 + hl);
    }

    // pointwise mapping: 1 (b,hl) pair per thread
    int pb = tid >> 3, phl = tid & 7;
    float c_reg = 0.f;

    // h-staging load mapping (per kgroup): 4 float4 per thread covering 32x64
    int hr = wt >> 4;            // 0..7 (+p*8)
    int hc = (wt & 15) * 4;      // 0..60

    __syncthreads();

#pragma unroll 1
    for (int t = 0; t < TT; ++t) {
        int tin = dir ? (TT - 1 - t) : t;
        int buf = t & 1;
        const float* hsrc = &g_h[dir][buf][0][0];

        // prefetch Zx for this step (hidden behind GEMM)
        float rzx[4];
        {
            const float* zp = &g_Zx[dir][tin * BB + pb][h0 + phl];
#pragma unroll
            for (int g = 0; g < 4; g++) rzx[g] = zp[g * 512];
        }

        // prefetch h tile for it=0
        float4 pre[4];
        {
            int kbase = kg * 128;
#pragma unroll
            for (int p = 0; p < 4; p++)
                pre[p] = *(const float4*)&hsrc[(kbase + hr + p * 8) * 64 + hc];
        }

        ull acc[2][4];
#pragma unroll
        for (int i = 0; i < 2; i++)
#pragma unroll
            for (int p = 0; p < 4; p++) acc[i][p] = 0ull;

#pragma unroll 1
        for (int it = 0; it < 4; ++it) {
            __syncthreads();
#pragma unroll
            for (int p = 0; p < 4; p++)
                *(float4*)&h_s[(hr + p * 8) * 64 + hc] = pre[p];
            __syncthreads();
            if (it < 3) {
                int kbase = kg * 128 + (it + 1) * 32;
#pragma unroll
                for (int p = 0; p < 4; p++)
                    pre[p] = *(const float4*)&hsrc[(kbase + hr + p * 8) * 64 + hc];
            }
            int kb = kg * 128 + it * 32;
#pragma unroll
            for (int kk = 0; kk < 32; ++kk) {
                float2 a = *(const float2*)&h_s[kk * 64 + ty * 2];
                ull a0, a1;
                DUP2(a0, a.x);
                DUP2(a1, a.y);
                const float* wrow = &w_s[(kb + kk) * 32 + tx * 8];
                ulonglong2 bq0 = *(const ulonglong2*)(wrow);
                ulonglong2 bq1 = *(const ulonglong2*)(wrow + 4);
                FMA2(acc[0][0], a0, bq0.x, acc[0][0]);
                FMA2(acc[0][1], a0, bq0.y, acc[0][1]);
                FMA2(acc[0][2], a0, bq1.x, acc[0][2]);
                FMA2(acc[0][3], a0, bq1.y, acc[0][3]);
                FMA2(acc[1][0], a1, bq0.x, acc[1][0]);
                FMA2(acc[1][1], a1, bq0.y, acc[1][1]);
                FMA2(acc[1][2], a1, bq1.x, acc[1][2]);
                FMA2(acc[1][3], a1, bq1.y, acc[1][3]);
            }
        }

        // stash partials
        __syncthreads();
        {
            float* zout = z_sb + kg * (64 * 33);
#pragma unroll
            for (int i = 0; i < 2; i++) {
                float* row = &zout[(ty * 2 + i) * 33 + tx * 8];
#pragma unroll
                for (int p = 0; p < 4; p++) {
                    unsigned lo, hi;
                    UNPK2(lo, hi, acc[i][p]);
                    row[p * 2 + 0] = __uint_as_float(lo);
                    row[p * 2 + 1] = __uint_as_float(hi);
                }
            }
        }
        __syncthreads();

        // pointwise LSTM update (c in registers), 1 pair per thread
        {
            int b = pb, hl = phl;
            float zi = rzx[0], zj = rzx[1], zf = rzx[2], zo = rzx[3];
#pragma unroll
            for (int g2 = 0; g2 < 4; g2++) {
                const float* zp = &z_sb[g2 * (64 * 33) + b * 33];
                zi += zp[0 + hl];
                zj += zp[8 + hl];
                zf += zp[16 + hl];
                zo += zp[24 + hl];
            }

            float ig = 1.f / (1.f + expf(-zi));
            float jg = tanhf(zj);
            float fg = 1.f / (1.f + expf(-(zf + 1.f)));
            float og = 1.f / (1.f + expf(-zo));

            float cnew = fg * c_reg + ig * jg;
            float hnew = og * tanhf(cnew);
            c_reg = cnew;

            g_h[dir][buf ^ 1][h0 + hl][b] = hnew;
            out[((size_t)b * TT + tin) * (2 * HH) + dir * HH + h0 + hl] = hnew;
        }

        grid_barrier(dir, (unsigned)(t + 1));
    }
}

extern "C" void kernel_launch(void* const* d_in, const int* in_sizes, int n_in,
                              void* d_out, int out_size) {
    const float* x   = (const float*)d_in[0];
    const float* Wfw = (const float*)d_in[1];
    const float* bfw = (const float*)d_in[2];
    const float* Wbw = (const float*)d_in[3];
    const float* bbw = (const float*)d_in[4];
    float* out = (float*)d_out;

    static int attr_done = 0;
    if (!attr_done) {
        cudaFuncSetAttribute(lstm_persist, cudaFuncAttributeMaxDynamicSharedMemorySize,
                             SMEM_FLOATS * sizeof(float));
        attr_done = 1;
    }

    // zero h state + barrier vars
    init_kernel<<<(2 * 2 * HH * BB + 255) / 256, 256>>>();

    // x-projection for both directions (bias folded in)
    pregemm<<<dim3(G4H / 128, (TT * BB) / 128, 2), 256>>>(x, Wfw, bfw, Wbw, bbw);

    // one persistent kernel runs all 512 steps for both directions
    lstm_persist<<<dim3(64, 2), 512, SMEM_FLOATS * sizeof(float)>>>(Wfw, Wbw, out);
}

// round 4
// speedup vs baseline: 1.2041x; 1.0220x over previous
#include <cuda_runtime.h>
#include <math.h>

#define BB 64
#define TT 512
#define DD 512
#define HH 512
#define G4H 2048  // 4*H

typedef unsigned long long ull;

// -------- device scratch (no cudaMalloc allowed) --------
__device__ float g_Zx[2][TT * BB][G4H];      // x-projection + bias, [dir][t*B+b][4H]
__device__ float g_h[2][2][HH][BB];          // hidden state, [dir][pingpong][k][b]
__device__ volatile unsigned g_phase[2];     // grid-barrier phase per direction
__device__ unsigned g_arrive[2];             // grid-barrier arrival counter per dir

// f32x2 packed FMA (sm_100+)
#define FMA2(d, a, b, c) \
    asm("fma.rn.f32x2 %0, %1, %2, %3;" : "=l"(d) : "l"(a), "l"(b), "l"(c))
#define DUP2(d, x) \
    asm("mov.b64 %0, {%1, %1};" : "=l"(d) : "r"(__float_as_uint(x)))
#define UNPK2(lo, hi, v) \
    asm("mov.b64 {%0, %1}, %2;" : "=r"(lo), "=r"(hi) : "l"(v))

__device__ __forceinline__ float fsigmoid(float x) {
    return 1.f / (1.f + __expf(-x));
}

// -------- x-projection GEMM (FFMA2) with init fused --------
// grid (N/128=16, M/128=256, 2), 256 threads. 128x128 tile, BK=16, double buffered.
__global__ void __launch_bounds__(256, 2)
pregemm(const float* __restrict__ x,
        const float* __restrict__ Wfw, const float* __restrict__ bfw,
        const float* __restrict__ Wbw, const float* __restrict__ bbw) {
    int dir = blockIdx.z;
    const float* Wm   = dir ? Wbw : Wfw;
    const float* bias = dir ? bbw : bfw;

    // fused init: 2 designated CTAs zero h-state and barrier vars for their dir
    if (blockIdx.x == 0 && blockIdx.y == 0) {
        float* hptr = &g_h[dir][0][0][0];
        for (int i = threadIdx.x; i < 2 * HH * BB; i += 256) hptr[i] = 0.f;
        if (threadIdx.x == 0) { g_phase[dir] = 0; g_arrive[dir] = 0; }
    }

    __shared__ float As[2][16][128];
    __shared__ float Bs[2][16][128];

    int tid = threadIdx.x;
    int n0 = blockIdx.x * 128;
    int m0 = blockIdx.y * 128;

    int a_m = tid >> 1;
    int a_k = (tid & 1) * 8;
    int gm  = m0 + a_m;
    int a_t = gm >> 6;
    int a_b = gm & 63;
    const float* a_ptr = x + ((size_t)a_b * TT + a_t) * DD + a_k;

    int b_k = tid >> 4;
    int b_n = (tid & 15) * 8;
    const float* b_ptr = Wm + (size_t)b_k * G4H + n0 + b_n;

    int ty = tid >> 4;
    int tx = tid & 15;

    ull acc[4][8];
#pragma unroll
    for (int i = 0; i < 4; i++)
#pragma unroll
        for (int j = 0; j < 8; j++) acc[i][j] = 0ull;

    float4 ar0 = *(const float4*)(a_ptr);
    float4 ar1 = *(const float4*)(a_ptr + 4);
    float4 br0 = *(const float4*)(b_ptr);
    float4 br1 = *(const float4*)(b_ptr + 4);
    {
        float* as = &As[0][0][a_m];
        as[(a_k + 0) * 128] = ar0.x; as[(a_k + 1) * 128] = ar0.y;
        as[(a_k + 2) * 128] = ar0.z; as[(a_k + 3) * 128] = ar0.w;
        as[(a_k + 4) * 128] = ar1.x; as[(a_k + 5) * 128] = ar1.y;
        as[(a_k + 6) * 128] = ar1.z; as[(a_k + 7) * 128] = ar1.w;
        *(float4*)&Bs[0][b_k][b_n] = br0;
        *(float4*)&Bs[0][b_k][b_n + 4] = br1;
    }
    __syncthreads();

    int buf = 0;
#pragma unroll 1
    for (int k0 = 0; k0 < DD / 16; ++k0) {
        if (k0 < DD / 16 - 1) {
            const float* ap = a_ptr + (k0 + 1) * 16;
            const float* bp = b_ptr + (size_t)(k0 + 1) * 16 * G4H;
            ar0 = *(const float4*)(ap);
            ar1 = *(const float4*)(ap + 4);
            br0 = *(const float4*)(bp);
            br1 = *(const float4*)(bp + 4);
        }
#pragma unroll
        for (int kk = 0; kk < 16; ++kk) {
            ulonglong2 a01 = *(const ulonglong2*)&As[buf][kk][ty * 8];
            ulonglong2 a23 = *(const ulonglong2*)&As[buf][kk][ty * 8 + 4];
            ull ap4[4] = {a01.x, a01.y, a23.x, a23.y};
            // j-half 0
            {
                float4 bv = *(const float4*)&Bs[buf][kk][tx * 8];
                ull bd[4];
                DUP2(bd[0], bv.x); DUP2(bd[1], bv.y); DUP2(bd[2], bv.z); DUP2(bd[3], bv.w);
#pragma unroll
                for (int i = 0; i < 4; i++)
#pragma unroll
                    for (int j = 0; j < 4; j++) FMA2(acc[i][j], ap4[i], bd[j], acc[i][j]);
            }
            // j-half 1
            {
                float4 bv = *(const float4*)&Bs[buf][kk][tx * 8 + 4];
                ull bd[4];
                DUP2(bd[0], bv.x); DUP2(bd[1], bv.y); DUP2(bd[2], bv.z); DUP2(bd[3], bv.w);
#pragma unroll
                for (int i = 0; i < 4; i++)
#pragma unroll
                    for (int j = 0; j < 4; j++) FMA2(acc[i][j + 4], ap4[i], bd[j], acc[i][j + 4]);
            }
        }
        if (k0 < DD / 16 - 1) {
            int nb = buf ^ 1;
            float* as = &As[nb][0][a_m];
            as[(a_k + 0) * 128] = ar0.x; as[(a_k + 1) * 128] = ar0.y;
            as[(a_k + 2) * 128] = ar0.z; as[(a_k + 3) * 128] = ar0.w;
            as[(a_k + 4) * 128] = ar1.x; as[(a_k + 5) * 128] = ar1.y;
            as[(a_k + 6) * 128] = ar1.z; as[(a_k + 7) * 128] = ar1.w;
            *(float4*)&Bs[nb][b_k][b_n] = br0;
            *(float4*)&Bs[nb][b_k][b_n + 4] = br1;
            __syncthreads();
            buf = nb;
        }
    }

    float bvals[8];
#pragma unroll
    for (int j = 0; j < 8; j++) bvals[j] = bias[n0 + tx * 8 + j];

#pragma unroll
    for (int i = 0; i < 4; i++) {
        float lo[8], hi[8];
#pragma unroll
        for (int j = 0; j < 8; j++) {
            unsigned l, h;
            UNPK2(l, h, acc[i][j]);
            lo[j] = __uint_as_float(l) + bvals[j];
            hi[j] = __uint_as_float(h) + bvals[j];
        }
        int m = m0 + ty * 8 + i * 2;
        float* r0 = &g_Zx[dir][m][n0 + tx * 8];
        float* r1 = &g_Zx[dir][m + 1][n0 + tx * 8];
        *(float4*)r0       = make_float4(lo[0], lo[1], lo[2], lo[3]);
        *(float4*)(r0 + 4) = make_float4(lo[4], lo[5], lo[6], lo[7]);
        *(float4*)r1       = make_float4(hi[0], hi[1], hi[2], hi[3]);
        *(float4*)(r1 + 4) = make_float4(hi[4], hi[5], hi[6], hi[7]);
    }
}

// -------- per-direction grid barrier (64 CTAs of a direction) --------
__device__ __forceinline__ void grid_barrier(int dir, unsigned target) {
    __syncthreads();
    if (threadIdx.x == 0) {
        __threadfence();   // orders writes + CCTL.IVALL (L1 invalidate)
        unsigned old = atomicAdd(&g_arrive[dir], 1);
        if (old == 63) {
            g_arrive[dir] = 0;
            __threadfence();
            g_phase[dir] = target;
        } else {
            while (g_phase[dir] < target) { __nanosleep(32); }
            __threadfence();   // L1 invalidate so h reads are fresh
        }
    }
    __syncthreads();
}

// -------- persistent recurrent kernel: all 512 steps, both dirs --------
// grid (64 h-blocks, 2 dirs), 512 threads = 4 K-groups x 128.
// smem: w_s resident 64KB + z partials ~33KB. h read directly from global/L2.
#define SM_W   (512 * 32)
#define SM_Z   (4 * 64 * 33)
#define SMEM_FLOATS (SM_W + SM_Z)

__global__ void __launch_bounds__(512, 1)
lstm_persist(const float* __restrict__ Wfw, const float* __restrict__ Wbw,
             float* __restrict__ out) {
    extern __shared__ float sm[];
    float* w_s  = sm;                   // [512][32]
    float* z_sb = sm + SM_W;            // [4][64][33]

    int dir = blockIdx.y;
    int hb  = blockIdx.x;
    int h0  = hb * 8;
    const float* Wm = dir ? Wbw : Wfw;

    int tid = threadIdx.x;     // 0..511
    int kg  = tid >> 7;        // K-group 0..3 (k in [kg*128, kg*128+128))
    int wt  = tid & 127;
    int ty  = wt >> 2;         // 0..31 -> batch pair ty*2
    int tx  = wt & 3;          // 0..3  -> cols tx*8

    // load resident W slice: rows DD..DD+511, gathered 32 cols (4 gates x 8 h)
    for (int idx = tid; idx < 4096; idx += 512) {
        int row = idx >> 3;
        int c4  = (idx & 7) * 4;
        int g   = c4 >> 3;
        int hl  = c4 & 7;
        *(float4*)&w_s[row * 32 + c4] =
            *(const float4*)(Wm + (size_t)(DD + row) * G4H + g * 512 + h0 + hl);
    }

    int pb = tid >> 3, phl = tid & 7;   // pointwise: 1 (b,h) per thread
    float c_reg = 0.f;

    const float* wp = &w_s[(kg * 128) * 32 + tx * 8];
    float* zout = z_sb + kg * (64 * 33);

    __syncthreads();

#pragma unroll 1
    for (int t = 0; t < TT; ++t) {
        int tin = dir ? (TT - 1 - t) : t;
        int buf = t & 1;
        const float* hp = &g_h[dir][buf][kg * 128][0] + ty * 2;

        // prefetch Zx for this step (consumed after GEMM; latency hidden)
        float rzx[4];
        {
            const float* zp = &g_Zx[dir][tin * BB + pb][h0 + phl];
#pragma unroll
            for (int g = 0; g < 4; g++) rzx[g] = zp[g * 512];
        }

        ull acc[2][4];
#pragma unroll
        for (int i = 0; i < 2; i++)
#pragma unroll
            for (int p = 0; p < 4; p++) acc[i][p] = 0ull;

#pragma unroll 8
        for (int kk = 0; kk < 128; ++kk) {
            float2 a = *(const float2*)(hp + kk * 64);
            ull a0, a1;
            DUP2(a0, a.x);
            DUP2(a1, a.y);
            const float* wrow = wp + kk * 32;
            ulonglong2 bq0 = *(const ulonglong2*)(wrow);
            ulonglong2 bq1 = *(const ulonglong2*)(wrow + 4);
            FMA2(acc[0][0], a0, bq0.x, acc[0][0]);
            FMA2(acc[0][1], a0, bq0.y, acc[0][1]);
            FMA2(acc[0][2], a0, bq1.x, acc[0][2]);
            FMA2(acc[0][3], a0, bq1.y, acc[0][3]);
            FMA2(acc[1][0], a1, bq0.x, acc[1][0]);
            FMA2(acc[1][1], a1, bq0.y, acc[1][1]);
            FMA2(acc[1][2], a1, bq1.x, acc[1][2]);
            FMA2(acc[1][3], a1, bq1.y, acc[1][3]);
        }

        // stash partials (z_sb safe: previous step's readers passed the barrier)
#pragma unroll
        for (int i = 0; i < 2; i++) {
            float* row = &zout[(ty * 2 + i) * 33 + tx * 8];
#pragma unroll
            for (int p = 0; p < 4; p++) {
                unsigned lo, hi;
                UNPK2(lo, hi, acc[i][p]);
                row[p * 2 + 0] = __uint_as_float(lo);
                row[p * 2 + 1] = __uint_as_float(hi);
            }
        }
        __syncthreads();

        // pointwise LSTM update (c in registers)
        {
            int b = pb, hl = phl;
            float zi = rzx[0], zj = rzx[1], zf = rzx[2], zo = rzx[3];
#pragma unroll
            for (int g2 = 0; g2 < 4; g2++) {
                const float* zp = &z_sb[g2 * (64 * 33) + b * 33];
                zi += zp[0 + hl];
                zj += zp[8 + hl];
                zf += zp[16 + hl];
                zo += zp[24 + hl];
            }

            float ig = fsigmoid(zi);
            float jg = tanhf(zj);
            float fg = fsigmoid(zf + 1.f);
            float og = fsigmoid(zo);

            float cnew = fg * c_reg + ig * jg;
            float hnew = og * tanhf(cnew);
            c_reg = cnew;

            g_h[dir][buf ^ 1][h0 + hl][b] = hnew;
            out[((size_t)b * TT + tin) * (2 * HH) + dir * HH + h0 + hl] = hnew;
        }

        grid_barrier(dir, (unsigned)(t + 1));
    }
}

extern "C" void kernel_launch(void* const* d_in, const int* in_sizes, int n_in,
                              void* d_out, int out_size) {
    const float* x   = (const float*)d_in[0];
    const float* Wfw = (const float*)d_in[1];
    const float* bfw = (const float*)d_in[2];
    const float* Wbw = (const float*)d_in[3];
    const float* bbw = (const float*)d_in[4];
    float* out = (float*)d_out;

    static int attr_done = 0;
    if (!attr_done) {
        cudaFuncSetAttribute(lstm_persist, cudaFuncAttributeMaxDynamicSharedMemorySize,
                             SMEM_FLOATS * sizeof(float));
        attr_done = 1;
    }

    // x-projection for both directions (bias folded in) + fused state init
    pregemm<<<dim3(G4H / 128, (TT * BB) / 128, 2), 256>>>(x, Wfw, bfw, Wbw, bbw);

    // one persistent kernel runs all 512 steps for both directions
    lstm_persist<<<dim3(64, 2), 512, SMEM_FLOATS * sizeof(float)>>>(Wfw, Wbw, out);
}

// round 5
// speedup vs baseline: 1.2206x; 1.0137x over previous
#include <cuda_runtime.h>
#include <math.h>

#define BB 64
#define TT 512
#define DD 512
#define HH 512
#define G4H 2048  // 4*H

typedef unsigned long long ull;

// -------- device scratch (no cudaMalloc allowed) --------
__device__ float g_Zx[2][TT * BB][G4H];      // x-projection + bias, [dir][t*B+b][4H]
__device__ float g_h[2][2][HH][BB];          // hidden state, [dir][pingpong][k][b]
__device__ volatile unsigned g_phase[2];     // grid-barrier phase per direction
__device__ unsigned g_arrive[2];             // grid-barrier arrival counter per dir

// f32x2 packed FMA (sm_100+)
#define FMA2(d, a, b, c) \
    asm("fma.rn.f32x2 %0, %1, %2, %3;" : "=l"(d) : "l"(a), "l"(b), "l"(c))
#define DUP2(d, x) \
    asm("mov.b64 %0, {%1, %1};" : "=l"(d) : "r"(__float_as_uint(x)))
#define UNPK2(lo, hi, v) \
    asm("mov.b64 {%0, %1}, %2;" : "=r"(lo), "=r"(hi) : "l"(v))

// cp.async 16B, .cg = L2-only (bypasses L1 -> coherent after grid barrier)
#define CP_ASYNC16(smem_u32, gptr) \
    asm volatile("cp.async.cg.shared.global [%0], [%1], 16;" :: "r"(smem_u32), "l"(gptr))
#define CP_COMMIT()  asm volatile("cp.async.commit_group;")
#define CP_WAIT0()   asm volatile("cp.async.wait_group 0;" ::: "memory")

__device__ __forceinline__ float fsigmoid(float x) {
    return 1.f / (1.f + __expf(-x));
}

// -------- x-projection GEMM (FFMA2) with init fused --------
__global__ void __launch_bounds__(256, 2)
pregemm(const float* __restrict__ x,
        const float* __restrict__ Wfw, const float* __restrict__ bfw,
        const float* __restrict__ Wbw, const float* __restrict__ bbw) {
    int dir = blockIdx.z;
    const float* Wm   = dir ? Wbw : Wfw;
    const float* bias = dir ? bbw : bfw;

    if (blockIdx.x == 0 && blockIdx.y == 0) {
        float* hptr = &g_h[dir][0][0][0];
        for (int i = threadIdx.x; i < 2 * HH * BB; i += 256) hptr[i] = 0.f;
        if (threadIdx.x == 0) { g_phase[dir] = 0; g_arrive[dir] = 0; }
    }

    __shared__ float As[2][16][128];
    __shared__ float Bs[2][16][128];

    int tid = threadIdx.x;
    int n0 = blockIdx.x * 128;
    int m0 = blockIdx.y * 128;

    int a_m = tid >> 1;
    int a_k = (tid & 1) * 8;
    int gm  = m0 + a_m;
    int a_t = gm >> 6;
    int a_b = gm & 63;
    const float* a_ptr = x + ((size_t)a_b * TT + a_t) * DD + a_k;

    int b_k = tid >> 4;
    int b_n = (tid & 15) * 8;
    const float* b_ptr = Wm + (size_t)b_k * G4H + n0 + b_n;

    int ty = tid >> 4;
    int tx = tid & 15;

    ull acc[4][8];
#pragma unroll
    for (int i = 0; i < 4; i++)
#pragma unroll
        for (int j = 0; j < 8; j++) acc[i][j] = 0ull;

    float4 ar0 = *(const float4*)(a_ptr);
    float4 ar1 = *(const float4*)(a_ptr + 4);
    float4 br0 = *(const float4*)(b_ptr);
    float4 br1 = *(const float4*)(b_ptr + 4);
    {
        float* as = &As[0][0][a_m];
        as[(a_k + 0) * 128] = ar0.x; as[(a_k + 1) * 128] = ar0.y;
        as[(a_k + 2) * 128] = ar0.z; as[(a_k + 3) * 128] = ar0.w;
        as[(a_k + 4) * 128] = ar1.x; as[(a_k + 5) * 128] = ar1.y;
        as[(a_k + 6) * 128] = ar1.z; as[(a_k + 7) * 128] = ar1.w;
        *(float4*)&Bs[0][b_k][b_n] = br0;
        *(float4*)&Bs[0][b_k][b_n + 4] = br1;
    }
    __syncthreads();

    int buf = 0;
#pragma unroll 1
    for (int k0 = 0; k0 < DD / 16; ++k0) {
        if (k0 < DD / 16 - 1) {
            const float* ap = a_ptr + (k0 + 1) * 16;
            const float* bp = b_ptr + (size_t)(k0 + 1) * 16 * G4H;
            ar0 = *(const float4*)(ap);
            ar1 = *(const float4*)(ap + 4);
            br0 = *(const float4*)(bp);
            br1 = *(const float4*)(bp + 4);
        }
#pragma unroll
        for (int kk = 0; kk < 16; ++kk) {
            ulonglong2 a01 = *(const ulonglong2*)&As[buf][kk][ty * 8];
            ulonglong2 a23 = *(const ulonglong2*)&As[buf][kk][ty * 8 + 4];
            ull ap4[4] = {a01.x, a01.y, a23.x, a23.y};
            {
                float4 bv = *(const float4*)&Bs[buf][kk][tx * 8];
                ull bd[4];
                DUP2(bd[0], bv.x); DUP2(bd[1], bv.y); DUP2(bd[2], bv.z); DUP2(bd[3], bv.w);
#pragma unroll
                for (int i = 0; i < 4; i++)
#pragma unroll
                    for (int j = 0; j < 4; j++) FMA2(acc[i][j], ap4[i], bd[j], acc[i][j]);
            }
            {
                float4 bv = *(const float4*)&Bs[buf][kk][tx * 8 + 4];
                ull bd[4];
                DUP2(bd[0], bv.x); DUP2(bd[1], bv.y); DUP2(bd[2], bv.z); DUP2(bd[3], bv.w);
#pragma unroll
                for (int i = 0; i < 4; i++)
#pragma unroll
                    for (int j = 0; j < 4; j++) FMA2(acc[i][j + 4], ap4[i], bd[j], acc[i][j + 4]);
            }
        }
        if (k0 < DD / 16 - 1) {
            int nb = buf ^ 1;
            float* as = &As[nb][0][a_m];
            as[(a_k + 0) * 128] = ar0.x; as[(a_k + 1) * 128] = ar0.y;
            as[(a_k + 2) * 128] = ar0.z; as[(a_k + 3) * 128] = ar0.w;
            as[(a_k + 4) * 128] = ar1.x; as[(a_k + 5) * 128] = ar1.y;
            as[(a_k + 6) * 128] = ar1.z; as[(a_k + 7) * 128] = ar1.w;
            *(float4*)&Bs[nb][b_k][b_n] = br0;
            *(float4*)&Bs[nb][b_k][b_n + 4] = br1;
            __syncthreads();
            buf = nb;
        }
    }

    float bvals[8];
#pragma unroll
    for (int j = 0; j < 8; j++) bvals[j] = bias[n0 + tx * 8 + j];

#pragma unroll
    for (int i = 0; i < 4; i++) {
        float lo[8], hi[8];
#pragma unroll
        for (int j = 0; j < 8; j++) {
            unsigned l, h;
            UNPK2(l, h, acc[i][j]);
            lo[j] = __uint_as_float(l) + bvals[j];
            hi[j] = __uint_as_float(h) + bvals[j];
        }
        int m = m0 + ty * 8 + i * 2;
        float* r0 = &g_Zx[dir][m][n0 + tx * 8];
        float* r1 = &g_Zx[dir][m + 1][n0 + tx * 8];
        *(float4*)r0       = make_float4(lo[0], lo[1], lo[2], lo[3]);
        *(float4*)(r0 + 4) = make_float4(lo[4], lo[5], lo[6], lo[7]);
        *(float4*)r1       = make_float4(hi[0], hi[1], hi[2], hi[3]);
        *(float4*)(r1 + 4) = make_float4(hi[4], hi[5], hi[6], hi[7]);
    }
}

// -------- per-direction grid barrier (64 CTAs of a direction) --------
__device__ __forceinline__ void grid_barrier(int dir, unsigned target) {
    __syncthreads();
    if (threadIdx.x == 0) {
        __threadfence();
        unsigned old = atomicAdd(&g_arrive[dir], 1);
        if (old == 63) {
            g_arrive[dir] = 0;
            __threadfence();
            g_phase[dir] = target;
        } else {
            while (g_phase[dir] < target) { __nanosleep(32); }
            __threadfence();
        }
    }
    __syncthreads();
}

// -------- persistent recurrent kernel --------
// grid (64 h-blocks, 2 dirs), 512 threads = 4 K-groups x 128.
// smem: W 64KB + full-h stage 128KB + z partials 33KB = 225KB (1 CTA/SM).
#define SM_W   (512 * 32)
#define SM_H   (512 * 64)
#define SM_Z   (4 * 64 * 33)
#define SMEM_FLOATS (SM_W + SM_H + SM_Z)

__global__ void __launch_bounds__(512, 1)
lstm_persist(const float* __restrict__ Wfw, const float* __restrict__ Wbw,
             float* __restrict__ out) {
    extern __shared__ float sm[];
    float* w_s  = sm;                   // [512][32]
    float* h_s  = sm + SM_W;            // [512][64]
    float* z_sb = sm + SM_W + SM_H;     // [4][64][33]

    int dir = blockIdx.y;
    int hb  = blockIdx.x;
    int h0  = hb * 8;
    const float* Wm = dir ? Wbw : Wfw;

    int tid = threadIdx.x;     // 0..511
    int kg  = tid >> 7;        // K-group 0..3
    int wt  = tid & 127;
    int ty  = wt >> 2;         // 0..31 -> batch pair ty*2
    int tx  = wt & 3;          // 0..3  -> cols tx*8

    // load resident W slice: rows DD..DD+511, gathered 32 cols (4 gates x 8 h)
    for (int idx = tid; idx < 4096; idx += 512) {
        int row = idx >> 3;
        int c4  = (idx & 7) * 4;
        int g   = c4 >> 3;
        int hl  = c4 & 7;
        *(float4*)&w_s[row * 32 + c4] =
            *(const float4*)(Wm + (size_t)(DD + row) * G4H + g * 512 + h0 + hl);
    }

    int pb = tid >> 3, phl = tid & 7;   // pointwise: 1 (b,h) per thread
    float c_reg = 0.f;

    const float* wp  = &w_s[(kg * 128) * 32 + tx * 8];
    const float* hsp = &h_s[(kg * 128) * 64 + ty * 2];
    float* zout = z_sb + kg * (64 * 33);

    unsigned h_s_u32 = (unsigned)__cvta_generic_to_shared(h_s);

    __syncthreads();

#pragma unroll 1
    for (int t = 0; t < TT; ++t) {
        int tin = dir ? (TT - 1 - t) : t;
        int buf = t & 1;

        // ---- stage full h (128KB) into smem via cp.async.cg (L2 path) ----
        {
            const float* hg = &g_h[dir][buf][0][0];
#pragma unroll
            for (int j = 0; j < 16; ++j) {
                int c = tid + j * 512;            // 16B chunk index, 8192 total
                CP_ASYNC16(h_s_u32 + c * 16, hg + c * 4);
            }
            CP_COMMIT();
        }

        // prefetch Zx for this step (DRAM latency hidden behind GEMM)
        float rzx[4];
        {
            const float* zp = &g_Zx[dir][tin * BB + pb][h0 + phl];
#pragma unroll
            for (int g = 0; g < 4; g++) rzx[g] = zp[g * 512];
        }

        CP_WAIT0();
        __syncthreads();

        ull acc[2][4];
#pragma unroll
        for (int i = 0; i < 2; i++)
#pragma unroll
            for (int p = 0; p < 4; p++) acc[i][p] = 0ull;

#pragma unroll 8
        for (int kk = 0; kk < 128; ++kk) {
            float2 a = *(const float2*)(hsp + kk * 64);
            ull a0, a1;
            DUP2(a0, a.x);
            DUP2(a1, a.y);
            const float* wrow = wp + kk * 32;
            ulonglong2 bq0 = *(const ulonglong2*)(wrow);
            ulonglong2 bq1 = *(const ulonglong2*)(wrow + 4);
            FMA2(acc[0][0], a0, bq0.x, acc[0][0]);
            FMA2(acc[0][1], a0, bq0.y, acc[0][1]);
            FMA2(acc[0][2], a0, bq1.x, acc[0][2]);
            FMA2(acc[0][3], a0, bq1.y, acc[0][3]);
            FMA2(acc[1][0], a1, bq0.x, acc[1][0]);
            FMA2(acc[1][1], a1, bq0.y, acc[1][1]);
            FMA2(acc[1][2], a1, bq1.x, acc[1][2]);
            FMA2(acc[1][3], a1, bq1.y, acc[1][3]);
        }

        // stash partials
#pragma unroll
        for (int i = 0; i < 2; i++) {
            float* row = &zout[(ty * 2 + i) * 33 + tx * 8];
#pragma unroll
            for (int p = 0; p < 4; p++) {
                unsigned lo, hi;
                UNPK2(lo, hi, acc[i][p]);
                row[p * 2 + 0] = __uint_as_float(lo);
                row[p * 2 + 1] = __uint_as_float(hi);
            }
        }
        __syncthreads();

        // pointwise LSTM update (c in registers)
        {
            int b = pb, hl = phl;
            float zi = rzx[0], zj = rzx[1], zf = rzx[2], zo = rzx[3];
#pragma unroll
            for (int g2 = 0; g2 < 4; g2++) {
                const float* zp = &z_sb[g2 * (64 * 33) + b * 33];
                zi += zp[0 + hl];
                zj += zp[8 + hl];
                zf += zp[16 + hl];
                zo += zp[24 + hl];
            }

            float ig = fsigmoid(zi);
            float jg = tanhf(zj);
            float fg = fsigmoid(zf + 1.f);
            float og = fsigmoid(zo);

            float cnew = fg * c_reg + ig * jg;
            float hnew = og * tanhf(cnew);
            c_reg = cnew;

            g_h[dir][buf ^ 1][h0 + hl][b] = hnew;
            out[((size_t)b * TT + tin) * (2 * HH) + dir * HH + h0 + hl] = hnew;
        }

        grid_barrier(dir, (unsigned)(t + 1));
    }
}

extern "C" void kernel_launch(void* const* d_in, const int* in_sizes, int n_in,
                              void* d_out, int out_size) {
    const float* x   = (const float*)d_in[0];
    const float* Wfw = (const float*)d_in[1];
    const float* bfw = (const float*)d_in[2];
    const float* Wbw = (const float*)d_in[3];
    const float* bbw = (const float*)d_in[4];
    float* out = (float*)d_out;

    static int attr_done = 0;
    if (!attr_done) {
        cudaFuncSetAttribute(lstm_persist, cudaFuncAttributeMaxDynamicSharedMemorySize,
                             SMEM_FLOATS * sizeof(float));
        attr_done = 1;
    }

    pregemm<<<dim3(G4H / 128, (TT * BB) / 128, 2), 256>>>(x, Wfw, bfw, Wbw, bbw);
    lstm_persist<<<dim3(64, 2), 512, SMEM_FLOATS * sizeof(float)>>>(Wfw, Wbw, out);
}

// round 6
// speedup vs baseline: 1.4178x; 1.1616x over previous
#include <cuda_runtime.h>
#include <math.h>

#define BB 64
#define TT 512
#define DD 512
#define HH 512
#define G4H 2048  // 4*H

typedef unsigned long long ull;

// -------- device scratch (no cudaMalloc allowed) --------
__device__ float g_Zx[2][TT * BB][G4H];      // x-projection + bias, [dir][t*B+b][4H]
__device__ float g_h[2][2][HH][BB];          // hidden state, [dir][pingpong][k][b]
__device__ volatile unsigned g_phase[2];     // grid-barrier phase per direction
__device__ unsigned g_arrive[2];             // grid-barrier arrival counter per dir

// f32x2 packed FMA (sm_100+)
#define FMA2(d, a, b, c) \
    asm("fma.rn.f32x2 %0, %1, %2, %3;" : "=l"(d) : "l"(a), "l"(b), "l"(c))
#define DUP2(d, x) \
    asm("mov.b64 %0, {%1, %1};" : "=l"(d) : "r"(__float_as_uint(x)))
#define UNPK2(lo, hi, v) \
    asm("mov.b64 {%0, %1}, %2;" : "=r"(lo), "=r"(hi) : "l"(v))

// cp.async 16B, .cg = L2-only (bypasses L1 -> coherent after grid barrier)
#define CP_ASYNC16(smem_u32, gptr) \
    asm volatile("cp.async.cg.shared.global [%0], [%1], 16;" :: "r"(smem_u32), "l"(gptr))
#define CP_COMMIT()  asm volatile("cp.async.commit_group;")
#define CP_WAIT0()   asm volatile("cp.async.wait_group 0;" ::: "memory")

__device__ __forceinline__ float fsigmoid(float x) {
    return 1.f / (1.f + __expf(-x));
}

// -------- x-projection GEMM (FFMA2) with init fused --------
__global__ void __launch_bounds__(256, 2)
pregemm(const float* __restrict__ x,
        const float* __restrict__ Wfw, const float* __restrict__ bfw,
        const float* __restrict__ Wbw, const float* __restrict__ bbw) {
    int dir = blockIdx.z;
    const float* Wm   = dir ? Wbw : Wfw;
    const float* bias = dir ? bbw : bfw;

    if (blockIdx.x == 0 && blockIdx.y == 0) {
        float* hptr = &g_h[dir][0][0][0];
        for (int i = threadIdx.x; i < 2 * HH * BB; i += 256) hptr[i] = 0.f;
        if (threadIdx.x == 0) { g_phase[dir] = 0; g_arrive[dir] = 0; }
    }

    __shared__ float As[2][16][128];
    __shared__ float Bs[2][16][128];

    int tid = threadIdx.x;
    int n0 = blockIdx.x * 128;
    int m0 = blockIdx.y * 128;

    int a_m = tid >> 1;
    int a_k = (tid & 1) * 8;
    int gm  = m0 + a_m;
    int a_t = gm >> 6;
    int a_b = gm & 63;
    const float* a_ptr = x + ((size_t)a_b * TT + a_t) * DD + a_k;

    int b_k = tid >> 4;
    int b_n = (tid & 15) * 8;
    const float* b_ptr = Wm + (size_t)b_k * G4H + n0 + b_n;

    int ty = tid >> 4;
    int tx = tid & 15;

    ull acc[4][8];
#pragma unroll
    for (int i = 0; i < 4; i++)
#pragma unroll
        for (int j = 0; j < 8; j++) acc[i][j] = 0ull;

    float4 ar0 = *(const float4*)(a_ptr);
    float4 ar1 = *(const float4*)(a_ptr + 4);
    float4 br0 = *(const float4*)(b_ptr);
    float4 br1 = *(const float4*)(b_ptr + 4);
    {
        float* as = &As[0][0][a_m];
        as[(a_k + 0) * 128] = ar0.x; as[(a_k + 1) * 128] = ar0.y;
        as[(a_k + 2) * 128] = ar0.z; as[(a_k + 3) * 128] = ar0.w;
        as[(a_k + 4) * 128] = ar1.x; as[(a_k + 5) * 128] = ar1.y;
        as[(a_k + 6) * 128] = ar1.z; as[(a_k + 7) * 128] = ar1.w;
        *(float4*)&Bs[0][b_k][b_n] = br0;
        *(float4*)&Bs[0][b_k][b_n + 4] = br1;
    }
    __syncthreads();

    int buf = 0;
#pragma unroll 1
    for (int k0 = 0; k0 < DD / 16; ++k0) {
        if (k0 < DD / 16 - 1) {
            const float* ap = a_ptr + (k0 + 1) * 16;
            const float* bp = b_ptr + (size_t)(k0 + 1) * 16 * G4H;
            ar0 = *(const float4*)(ap);
            ar1 = *(const float4*)(ap + 4);
            br0 = *(const float4*)(bp);
            br1 = *(const float4*)(bp + 4);
        }
#pragma unroll
        for (int kk = 0; kk < 16; ++kk) {
            ulonglong2 a01 = *(const ulonglong2*)&As[buf][kk][ty * 8];
            ulonglong2 a23 = *(const ulonglong2*)&As[buf][kk][ty * 8 + 4];
            ull ap4[4] = {a01.x, a01.y, a23.x, a23.y};
            {
                float4 bv = *(const float4*)&Bs[buf][kk][tx * 8];
                ull bd[4];
                DUP2(bd[0], bv.x); DUP2(bd[1], bv.y); DUP2(bd[2], bv.z); DUP2(bd[3], bv.w);
#pragma unroll
                for (int i = 0; i < 4; i++)
#pragma unroll
                    for (int j = 0; j < 4; j++) FMA2(acc[i][j], ap4[i], bd[j], acc[i][j]);
            }
            {
                float4 bv = *(const float4*)&Bs[buf][kk][tx * 8 + 4];
                ull bd[4];
                DUP2(bd[0], bv.x); DUP2(bd[1], bv.y); DUP2(bd[2], bv.z); DUP2(bd[3], bv.w);
#pragma unroll
                for (int i = 0; i < 4; i++)
#pragma unroll
                    for (int j = 0; j < 4; j++) FMA2(acc[i][j + 4], ap4[i], bd[j], acc[i][j + 4]);
            }
        }
        if (k0 < DD / 16 - 1) {
            int nb = buf ^ 1;
            float* as = &As[nb][0][a_m];
            as[(a_k + 0) * 128] = ar0.x; as[(a_k + 1) * 128] = ar0.y;
            as[(a_k + 2) * 128] = ar0.z; as[(a_k + 3) * 128] = ar0.w;
            as[(a_k + 4) * 128] = ar1.x; as[(a_k + 5) * 128] = ar1.y;
            as[(a_k + 6) * 128] = ar1.z; as[(a_k + 7) * 128] = ar1.w;
            *(float4*)&Bs[nb][b_k][b_n] = br0;
            *(float4*)&Bs[nb][b_k][b_n + 4] = br1;
            __syncthreads();
            buf = nb;
        }
    }

    float bvals[8];
#pragma unroll
    for (int j = 0; j < 8; j++) bvals[j] = bias[n0 + tx * 8 + j];

#pragma unroll
    for (int i = 0; i < 4; i++) {
        float lo[8], hi[8];
#pragma unroll
        for (int j = 0; j < 8; j++) {
            unsigned l, h;
            UNPK2(l, h, acc[i][j]);
            lo[j] = __uint_as_float(l) + bvals[j];
            hi[j] = __uint_as_float(h) + bvals[j];
        }
        int m = m0 + ty * 8 + i * 2;
        float* r0 = &g_Zx[dir][m][n0 + tx * 8];
        float* r1 = &g_Zx[dir][m + 1][n0 + tx * 8];
        *(float4*)r0       = make_float4(lo[0], lo[1], lo[2], lo[3]);
        *(float4*)(r0 + 4) = make_float4(lo[4], lo[5], lo[6], lo[7]);
        *(float4*)r1       = make_float4(hi[0], hi[1], hi[2], hi[3]);
        *(float4*)(r1 + 4) = make_float4(hi[4], hi[5], hi[6], hi[7]);
    }
}

// -------- per-direction grid barrier (64 CTAs of a direction) --------
__device__ __forceinline__ void grid_barrier(int dir, unsigned target) {
    __syncthreads();
    if (threadIdx.x == 0) {
        __threadfence();
        unsigned old = atomicAdd(&g_arrive[dir], 1);
        if (old == 63) {
            g_arrive[dir] = 0;
            __threadfence();
            g_phase[dir] = target;
        } else {
            while (g_phase[dir] < target) { }   // tight spin (no nanosleep)
            __threadfence();
        }
    }
    __syncthreads();
}

// -------- persistent recurrent kernel --------
// grid (64 h-blocks, 2 dirs), 512 threads = 8 K-groups x 64.
// Thread tile: 4 batch x 8 gate-cols over K=64 per group (16 FMA2 / 3 LDS.128 per k).
// smem: W 64KB + h stage 128KB (z partials aliased into it) = 192KB (1 CTA/SM).
#define SM_W   (512 * 32)
#define SM_H   (512 * 64)
#define SMEM_FLOATS (SM_W + SM_H)

__global__ void __launch_bounds__(512, 1)
lstm_persist(const float* __restrict__ Wfw, const float* __restrict__ Wbw,
             float* __restrict__ out) {
    extern __shared__ float sm[];
    float* w_s  = sm;                   // [512][32]
    float* h_s  = sm + SM_W;            // [512][64], z partials alias after GEMM

    int dir = blockIdx.y;
    int hb  = blockIdx.x;
    int h0  = hb * 8;
    const float* Wm = dir ? Wbw : Wfw;

    int tid = threadIdx.x;     // 0..511
    int kg  = tid >> 6;        // K-group 0..7 (k in [kg*64, kg*64+64))
    int wt  = tid & 63;
    int ty  = wt >> 2;         // 0..15 -> batch rows ty*4
    int tx  = wt & 3;          // 0..3  -> cols tx*8

    // load resident W slice: rows DD..DD+511, gathered 32 cols (4 gates x 8 h)
    for (int idx = tid; idx < 4096; idx += 512) {
        int row = idx >> 3;
        int c4  = (idx & 7) * 4;
        int g   = c4 >> 3;
        int hl  = c4 & 7;
        *(float4*)&w_s[row * 32 + c4] =
            *(const float4*)(Wm + (size_t)(DD + row) * G4H + g * 512 + h0 + hl);
    }

    int pb = tid >> 3, phl = tid & 7;   // pointwise: 1 (b,h) per thread
    float c_reg = 0.f;

    const float* wp  = &w_s[(kg * 64) * 32 + tx * 8];
    const float* hsp = &h_s[(kg * 64) * 64 + ty * 4];
    float* zout = h_s + kg * (64 * 33);           // aliased z region [8][64][33]

    unsigned h_s_u32 = (unsigned)__cvta_generic_to_shared(h_s);

    __syncthreads();

#pragma unroll 1
    for (int t = 0; t < TT; ++t) {
        int tin = dir ? (TT - 1 - t) : t;
        int buf = t & 1;

        // ---- stage full h (128KB) into smem via cp.async.cg (L2 path) ----
        {
            const float* hg = &g_h[dir][buf][0][0];
#pragma unroll
            for (int j = 0; j < 16; ++j) {
                int c = tid + j * 512;            // 16B chunk index, 8192 total
                CP_ASYNC16(h_s_u32 + c * 16, hg + c * 4);
            }
            CP_COMMIT();
        }

        // prefetch Zx for this step (consumed in pointwise; latency hidden)
        float rzx[4];
        {
            const float* zp = &g_Zx[dir][tin * BB + pb][h0 + phl];
#pragma unroll
            for (int g = 0; g < 4; g++) rzx[g] = zp[g * 512];
        }

        CP_WAIT0();
        __syncthreads();

        ull acc[4][4];
#pragma unroll
        for (int i = 0; i < 4; i++)
#pragma unroll
            for (int p = 0; p < 4; p++) acc[i][p] = 0ull;

#pragma unroll 4
        for (int kk = 0; kk < 64; ++kk) {
            float4 hv = *(const float4*)(hsp + kk * 64);
            ull a0, a1, a2, a3;
            DUP2(a0, hv.x);
            DUP2(a1, hv.y);
            DUP2(a2, hv.z);
            DUP2(a3, hv.w);
            const float* wrow = wp + kk * 32;
            ulonglong2 bq0 = *(const ulonglong2*)(wrow);
            ulonglong2 bq1 = *(const ulonglong2*)(wrow + 4);
            FMA2(acc[0][0], a0, bq0.x, acc[0][0]);
            FMA2(acc[0][1], a0, bq0.y, acc[0][1]);
            FMA2(acc[0][2], a0, bq1.x, acc[0][2]);
            FMA2(acc[0][3], a0, bq1.y, acc[0][3]);
            FMA2(acc[1][0], a1, bq0.x, acc[1][0]);
            FMA2(acc[1][1], a1, bq0.y, acc[1][1]);
            FMA2(acc[1][2], a1, bq1.x, acc[1][2]);
            FMA2(acc[1][3], a1, bq1.y, acc[1][3]);
            FMA2(acc[2][0], a2, bq0.x, acc[2][0]);
            FMA2(acc[2][1], a2, bq0.y, acc[2][1]);
            FMA2(acc[2][2], a2, bq1.x, acc[2][2]);
            FMA2(acc[2][3], a2, bq1.y, acc[2][3]);
            FMA2(acc[3][0], a3, bq0.x, acc[3][0]);
            FMA2(acc[3][1], a3, bq0.y, acc[3][1]);
            FMA2(acc[3][2], a3, bq1.x, acc[3][2]);
            FMA2(acc[3][3], a3, bq1.y, acc[3][3]);
        }

        // all K-groups done reading h_s -> safe to alias z into it
        __syncthreads();
#pragma unroll
        for (int i = 0; i < 4; i++) {
            float* row = &zout[(ty * 4 + i) * 33 + tx * 8];
#pragma unroll
            for (int p = 0; p < 4; p++) {
                unsigned lo, hi;
                UNPK2(lo, hi, acc[i][p]);
                row[p * 2 + 0] = __uint_as_float(lo);
                row[p * 2 + 1] = __uint_as_float(hi);
            }
        }
        __syncthreads();

        // pointwise LSTM update (c in registers)
        {
            int b = pb, hl = phl;
            float zi = rzx[0], zj = rzx[1], zf = rzx[2], zo = rzx[3];
#pragma unroll
            for (int g2 = 0; g2 < 8; g2++) {
                const float* zp = &h_s[g2 * (64 * 33) + b * 33];
                zi += zp[0 + hl];
                zj += zp[8 + hl];
                zf += zp[16 + hl];
                zo += zp[24 + hl];
            }

            float ig = fsigmoid(zi);
            float jg = tanhf(zj);
            float fg = fsigmoid(zf + 1.f);
            float og = fsigmoid(zo);

            float cnew = fg * c_reg + ig * jg;
            float hnew = og * tanhf(cnew);
            c_reg = cnew;

            g_h[dir][buf ^ 1][h0 + hl][b] = hnew;
            out[((size_t)b * TT + tin) * (2 * HH) + dir * HH + h0 + hl] = hnew;
        }

        grid_barrier(dir, (unsigned)(t + 1));
    }
}

extern "C" void kernel_launch(void* const* d_in, const int* in_sizes, int n_in,
                              void* d_out, int out_size) {
    const float* x   = (const float*)d_in[0];
    const float* Wfw = (const float*)d_in[1];
    const float* bfw = (const float*)d_in[2];
    const float* Wbw = (const float*)d_in[3];
    const float* bbw = (const float*)d_in[4];
    float* out = (float*)d_out;

    static int attr_done = 0;
    if (!attr_done) {
        cudaFuncSetAttribute(lstm_persist, cudaFuncAttributeMaxDynamicSharedMemorySize,
                             SMEM_FLOATS * sizeof(float));
        attr_done = 1;
    }

    pregemm<<<dim3(G4H / 128, (TT * BB) / 128, 2), 256>>>(x, Wfw, bfw, Wbw, bbw);
    lstm_persist<<<dim3(64, 2), 512, SMEM_FLOATS * sizeof(float)>>>(Wfw, Wbw, out);
}